// round 12
// baseline (speedup 1.0000x reference)
#include <cuda_runtime.h>
#include <math.h>
#include <stdint.h>

// Problem constants
#define B_  2
#define C_  64
#define H_  128
#define W_  128
#define HW_ (H_*W_)          // 16384
#define HID 16
#define OFC 18
#define NPT 9
#define KTOT (C_*NPT)        // 576
#define PIXT (B_*HW_)        // 32768
#define HP_  130
#define WP_  130
#define HWP_ (HP_*WP_)       // 16900

// ---- device scratch (no runtime allocation allowed) ----
__device__ float g_f  [B_*HID*HW_];       // offset-branch feature [B,16,H,W]
__device__ float g_off[B_*OFC*HW_];       // offsets               [B,18,H,W]
__device__ float g_wt2[288*128];          // chunk-packed w_out (see k_padT)
__device__ float g_xp [B_*HWP_*C_ + 8];   // TRANSPOSED padded input [B][130*130][64]

// packed fp32x2 FMA (per-component accumulate: pairs carry adjacent k)
#define FMA2(d,a,b) asm("fma.rn.f32x2 %0, %1, %2, %0;" : "+l"(d) : "l"(a), "l"(b))

__device__ __forceinline__ void cp_async16(uint32_t dst, const void* src) {
    asm volatile("cp.async.ca.shared.global [%0], [%1], 16;" :: "r"(dst), "l"(src));
}
#define CP_COMMIT() asm volatile("cp.async.commit_group;")
#define CP_WAIT0()  asm volatile("cp.async.wait_group 0;")

// ============================================================
// K_padT: zero-pad + TRANSPOSE x into g_xp[b][hw_p][c]
//  tail: pack w_out into g_wt2:
//   chunk c2 = n*2 + (ci>>5)  (18 chunks of 32 k each; n = sample pt)
//   row R = c2*16 + ((ci&31)>>1)   (k-pair rows, 16 per chunk)
//   col  = j*32 + g*4 + o2*2 + q   (g=oc>>3, j=(oc&7)>>1, o2=oc&1, q=ci&1)
// ============================================================
#define PAD_BLKS (B_*HP_)
#define W0_BLKS  ((KTOT*C_ + 255)/256)
__global__ __launch_bounds__(256)
void k_padT(const float* __restrict__ x, const float* __restrict__ w) {
    int blk = blockIdx.x;
    int tid = threadIdx.x;
    if (blk < PAD_BLKS) {
        __shared__ float ts[WP_ * 65];     // [w][c] pitch 65 (conflict-free)
        int b = blk / HP_, h = blk % HP_;
        if (h >= 1 && h <= H_) {
            const float* xr = x + (size_t)b * C_ * HW_ + (h - 1) * W_;
            for (int e = tid; e < C_ * W_; e += 256) {
                int c = e >> 7, w2 = e & 127;            // coalesced read along w
                ts[(w2 + 1) * 65 + c] = xr[c * HW_ + w2];
            }
            if (tid < 2 * C_) {                          // border columns
                int c = tid & 63, side = tid >> 6;
                ts[(side ? (WP_ - 1) * 65 : 0) + c] = 0.f;
            }
        } else {
            for (int e = tid; e < WP_ * C_; e += 256) {
                int w2 = e >> 6, c = e & 63;
                ts[w2 * 65 + c] = 0.f;
            }
        }
        __syncthreads();
        float* dst = g_xp + ((size_t)b * HP_ + h) * WP_ * C_;
        for (int e = tid; e < WP_ * C_; e += 256) {
            int w2 = e >> 6, c = e & 63;
            dst[e] = ts[w2 * 65 + c];                    // coalesced write along c
        }
    } else {
        int t = (blk - PAD_BLKS) * 256 + tid;
        if (t < KTOT * C_) {
            int oc = t / KTOT, r = t - oc * KTOT;        // r = ci*9 + n
            int ci = r / 9, n = r - ci * 9;
            int c2 = n * 2 + (ci >> 5);
            int R  = c2 * 16 + ((ci & 31) >> 1);
            int q  = ci & 1;
            int g  = oc >> 3, j = (oc & 7) >> 1, o2 = oc & 1;
            int col = j * 32 + g * 4 + o2 * 2 + q;
            g_wt2[R * 128 + col] = w[t];
        }
    }
}

// ============================================================
// K1: f = relu(bn(conv1x1_{64->16}(x)))
// ============================================================
__global__ void k1_conv1(const float* __restrict__ x,
                         const float* __restrict__ w1,
                         const float* __restrict__ g1,
                         const float* __restrict__ b1,
                         const float* __restrict__ m1,
                         const float* __restrict__ v1) {
    __shared__ float ws[C_][HID];
    __shared__ float inv_s[HID], beta_s[HID];
    int tid = threadIdx.x;
    for (int e = tid; e < HID * C_; e += 256) {
        int o = e / C_, c = e % C_;
        ws[c][o] = w1[e];
    }
    if (tid < HID) {
        float inv = g1[tid] * rsqrtf(v1[tid] + 1e-5f);
        inv_s[tid] = inv;
        beta_s[tid] = b1[tid] - m1[tid] * inv;
    }
    __syncthreads();

    int p = blockIdx.x * 256 + tid;
    int b = p >> 14, hw = p & (HW_ - 1);
    const float* xb = x + (size_t)b * C_ * HW_ + hw;

    float acc[HID];
#pragma unroll
    for (int o = 0; o < HID; o++) acc[o] = 0.f;
    for (int c = 0; c < C_; c++) {
        float xv = xb[c * HW_];
#pragma unroll
        for (int o = 0; o < HID; o++) acc[o] += ws[c][o] * xv;
    }
    float* fb = g_f + (size_t)b * HID * HW_ + hw;
#pragma unroll
    for (int o = 0; o < HID; o++)
        fb[o * HW_] = fmaxf(acc[o] * inv_s[o] + beta_s[o], 0.f);
}

// ============================================================
// K2 (tiled): off = relu(bn3(1x1( relu(bn2(3x3(f))) )))
// ============================================================
__global__ __launch_bounds__(256)
void k2_offsets(const float* __restrict__ wdw,
                const float* __restrict__ g2, const float* __restrict__ b2,
                const float* __restrict__ m2, const float* __restrict__ v2,
                const float* __restrict__ wc2,
                const float* __restrict__ g3, const float* __restrict__ b3,
                const float* __restrict__ m3, const float* __restrict__ v3) {
    __shared__ float fs[HID * 18 * 18];
    __shared__ float wdw_s[OFC * HID * 9];
    __shared__ float wc2_s[OFC * OFC];
    __shared__ float inv2_s[OFC], beta2_s[OFC], inv3_s[OFC], beta3_s[OFC];
    int tid = threadIdx.x;

    int blk = blockIdx.x;
    int b = blk >> 6, t = blk & 63;
    int h0 = (t >> 3) << 4, w0 = (t & 7) << 4;

    for (int e = tid; e < OFC * HID * 9; e += 256) wdw_s[e] = wdw[e];
    for (int e = tid; e < OFC * OFC; e += 256)     wc2_s[e] = wc2[e];
    if (tid < OFC) {
        float i2 = g2[tid] * rsqrtf(v2[tid] + 1e-5f);
        inv2_s[tid] = i2; beta2_s[tid] = b2[tid] - m2[tid] * i2;
        float i3 = g3[tid] * rsqrtf(v3[tid] + 1e-5f);
        inv3_s[tid] = i3; beta3_s[tid] = b3[tid] - m3[tid] * i3;
    }

    const float* fb = g_f + (size_t)b * HID * HW_;
    for (int e = tid; e < HID * 324; e += 256) {
        int ci = e / 324, r = e - ci * 324;
        int hh = r / 18, ww = r - hh * 18;
        int h = h0 - 1 + hh, w = w0 - 1 + ww;
        float v = 0.f;
        if (h >= 0 && h < H_ && w >= 0 && w < W_)
            v = fb[ci * HW_ + h * W_ + w];
        fs[e] = v;
    }
    __syncthreads();

    int ty2 = tid >> 4, tx2 = tid & 15;
    float acc[OFC];
#pragma unroll
    for (int o = 0; o < OFC; o++) acc[o] = 0.f;

    for (int ci = 0; ci < HID; ci++) {
        float fv[9];
        const float* fsc = fs + ci * 324;
#pragma unroll
        for (int dh = 0; dh < 3; dh++)
#pragma unroll
            for (int dw = 0; dw < 3; dw++)
                fv[dh * 3 + dw] = fsc[(ty2 + dh) * 18 + (tx2 + dw)];
        const float* wp = wdw_s + ci * 9;
#pragma unroll
        for (int o = 0; o < OFC; o++) {
            const float* wo = wp + o * (HID * 9);
            float a = acc[o];
#pragma unroll
            for (int k = 0; k < 9; k++) a += wo[k] * fv[k];
            acc[o] = a;
        }
    }
    float tv[OFC];
#pragma unroll
    for (int o = 0; o < OFC; o++)
        tv[o] = fmaxf(acc[o] * inv2_s[o] + beta2_s[o], 0.f);

    int h = h0 + ty2, w = w0 + tx2;
    float* op = g_off + (size_t)b * OFC * HW_ + h * W_ + w;
#pragma unroll
    for (int o2 = 0; o2 < OFC; o2++) {
        float a = 0.f;
#pragma unroll
        for (int o = 0; o < OFC; o++) a += wc2_s[o2 * OFC + o] * tv[o];
        op[o2 * HW_] = fmaxf(a * inv3_s[o2] + beta3_s[o2], 0.f);
    }
}

// ============================================================
// K3: fused bilinear sampler + SGEMM (k-paired f32x2), 8px x 8oc tiles
//   block = 128 threads, tile = 128 px x 64 oc, 18 chunks of 32 k
//   smem: compact meta 16B/sample (18.4KB) + slab dbuf [2][128][36]
//         (36.9KB) + B dbuf [2][16 kp][128] via cp.async (16.4KB) = 71.7KB
// ============================================================
#define APITCH 36
#define SLABN (128*APITCH)                  // 4608 floats per slab buffer
#define SMEM_SLAB 18432
#define SMEM_B    (SMEM_SLAB + 2*SLABN*4)   // 55296
#define K3_SMEM   (SMEM_B + 2*2048*4)       // 71680

__global__ __launch_bounds__(128, 2)
void k3_main(const float* __restrict__ x, float* __restrict__ out) {
    extern __shared__ char smem[];
    float4* meta4 = (float4*)smem;                 // [128 px][9 pts], 16B each
    float*  slab  = (float*)(smem + SMEM_SLAB);    // [2][128][APITCH]
    float*  bsm   = (float*)(smem + SMEM_B);       // [2][2048]

    int tid = threadIdx.x;
    int blk = blockIdx.x;                 // 256 blocks
    int b = blk >> 7;
    int tile = blk & 127;
    int h0 = (tile >> 3) << 3;            // 16 h-tiles of 8
    int w0 = (tile & 7) << 4;             // 8 w-tiles of 16

    uint32_t bsm_u32 = (uint32_t)__cvta_generic_to_shared(bsm) + tid * 16;
#define STAGE_B(buf, cc)                                                      \
    {                                                                         \
        const float* src = g_wt2 + (cc) * 2048 + tid * 4;                     \
        uint32_t dst = bsm_u32 + (buf) * 8192;                                \
        cp_async16(dst,        src);                                          \
        cp_async16(dst + 2048, src + 512);                                    \
        cp_async16(dst + 4096, src + 1024);                                   \
        cp_async16(dst + 6144, src + 1536);                                   \
        CP_COMMIT();                                                          \
    }

    STAGE_B(0, 0)

    // ---- compact bilinear metadata: 128 px x 9 pts, 16B each ----
    const float* offp = g_off + (size_t)b * OFC * HW_;
    for (int e = tid; e < 128 * NPT; e += 128) {
        int px = e / 9, n = e - px * 9;
        int h = h0 + (px >> 4), w = w0 + (px & 15);
        int hw = h * W_ + w;
        float offx = offp[n * HW_ + hw];
        float offy = offp[(NPT + n) * HW_ + hw];
        float pxf = (float)(h + 1) + (float)(n / 3 - 1) + offx;
        float pyf = (float)(w + 1) + (float)(n % 3 - 1) + offy;
        float flx = floorf(pxf), fly = floorf(pyf);
        float qltx = fminf(fmaxf(flx, 0.f), 129.f);
        float qlty = fminf(fmaxf(fly, 0.f), 129.f);
        float qrbx = fminf(fmaxf(flx + 1.f, 0.f), 129.f);
        float qrby = fminf(fmaxf(fly + 1.f, 0.f), 129.f);
        float pxc = fminf(fmaxf(pxf, 0.f), 129.f);
        float pyc = fminf(fmaxf(pyf, 0.f), 129.f);
        float ax = qltx - pxc;             // 0 whenever x clamps (both corners equal)
        float ay = qlty - pyc;
        unsigned clampx = (qltx == qrbx) ? 0x80000000u : 0u;
        unsigned clampy = (qlty == qrby) ? 0x80000000u : 0u;
        int ltx = (int)qltx, lty = (int)qlty, rbx = (int)qrbx, rby = (int)qrby;
        unsigned i_lt = (unsigned)(ltx * WP_ + lty);
        unsigned i_rb = (unsigned)(rbx * WP_ + rby);
        unsigned i_lb = (unsigned)(ltx * WP_ + rby);
        unsigned i_rt = (unsigned)(rbx * WP_ + lty);
        unsigned u0 = i_lt | (i_rb << 16) | clampx;
        unsigned u1 = i_lb | (i_rt << 16) | clampy;
        meta4[e] = make_float4(__uint_as_float(u0), __uint_as_float(u1), ax, ay);
    }

    const float* xpb = g_xp + (size_t)b * HWP_ * C_;
    const int lane = tid & 31;
    const int wid  = tid >> 5;
    const int lc   = lane & 15;           // channel-pair within chunk
    const int half = lane >> 4;           // px parity within iter

    // warp-cooperative gather: warp w -> px [32w, 32w+32), 2 px per iter,
    // lanes 0-15 / 16-31 split px; each lane reads 2 channels (contig 8B)
#define GATHER_CHUNK(dbuf, cc)                                                \
    {                                                                         \
        int n_ = (cc) >> 1;                                                   \
        const float* xch = xpb + ((cc) & 1) * 32 + 2 * lc;                    \
        float* sd = slab + (dbuf) * SLABN + 2 * lc;                           \
        _Pragma("unroll 4")                                                   \
        for (int it = 0; it < 16; it++) {                                     \
            int px = wid * 32 + it * 2 + half;                                \
            float4 mm = meta4[px * 9 + n_];                                   \
            unsigned u0 = __float_as_uint(mm.x), u1 = __float_as_uint(mm.y);  \
            float ax = mm.z, ay = mm.w;                                       \
            float wxl = 1.f + ax, wyl = 1.f + ay;                             \
            float wxr = (u0 & 0x80000000u) ? 1.f : -ax;                       \
            float wyr = (u1 & 0x80000000u) ? 1.f : -ay;                       \
            float gx = wxl * wyl, gy = wxr * wyr;                             \
            float gz = wxl * wyr, gw = wxr * wyl;                             \
            float2 lt = *(const float2*)(xch + ((u0 & 0x7fffu) << 6));        \
            float2 rb = *(const float2*)(xch + (((u0 >> 16) & 0x7fffu) << 6));\
            float2 lb = *(const float2*)(xch + ((u1 & 0x7fffu) << 6));        \
            float2 rt = *(const float2*)(xch + (((u1 >> 16) & 0x7fffu) << 6));\
            float v0 = gx*lt.x + gy*rb.x + gz*lb.x + gw*rt.x;                 \
            float v1 = gx*lt.y + gy*rb.y + gz*lb.y + gw*rt.y;                 \
            *(float2*)(sd + px * APITCH) = make_float2(v0, v1);               \
        }                                                                     \
    }

    CP_WAIT0();
    __syncthreads();               // meta + B(0) visible
    GATHER_CHUNK(0, 0)
    __syncthreads();               // slab(0) visible

    const int g  = tid & 7;        // oc-group: oc = g*8 .. g*8+7
    const int pg = tid >> 3;       // px-group: px = pg*8 .. pg*8+7

    unsigned long long acc[8][8];  // [px][oc], f32x2 (even-k, odd-k) partials
#pragma unroll
    for (int i = 0; i < 8; i++)
#pragma unroll
        for (int j = 0; j < 8; j++) acc[i][j] = 0ull;

    // ---- pipelined chunk loop ----
    for (int c = 0; c < 18; c++) {
        if (c < 17) {
            STAGE_B((c + 1) & 1, c + 1)
            GATHER_CHUNK((c + 1) & 1, c + 1)
        }

        const float* ab = slab + (c & 1) * SLABN + pg * (8 * APITCH);
        const float* bp = bsm + (c & 1) * 2048 + g * 4;
#pragma unroll 2
        for (int kq = 0; kq < 8; kq++) {          // 4 k per iter (2 k-pairs)
            ulonglong2 av[8];
#pragma unroll
            for (int p = 0; p < 8; p++)
                av[p] = *(const ulonglong2*)(ab + p * APITCH + kq * 4);
#pragma unroll
            for (int hh = 0; hh < 2; hh++) {
                const float* row = bp + (kq * 2 + hh) * 128;
                ulonglong2 b0 = *(const ulonglong2*)(row);
                ulonglong2 b1 = *(const ulonglong2*)(row + 32);
                ulonglong2 b2 = *(const ulonglong2*)(row + 64);
                ulonglong2 b3 = *(const ulonglong2*)(row + 96);
#pragma unroll
                for (int p = 0; p < 8; p++) {
                    unsigned long long a = hh ? av[p].y : av[p].x;
                    FMA2(acc[p][0], a, b0.x); FMA2(acc[p][1], a, b0.y);
                    FMA2(acc[p][2], a, b1.x); FMA2(acc[p][3], a, b1.y);
                    FMA2(acc[p][4], a, b2.x); FMA2(acc[p][5], a, b2.y);
                    FMA2(acc[p][6], a, b3.x); FMA2(acc[p][7], a, b3.y);
                }
            }
        }

        CP_WAIT0();
        __syncthreads();           // publish slab(c+1) + B(c+1)
    }

    // ---- epilogue: fold k-partials, stage via smem, coalesced residual ----
    __syncthreads();
    float* sa = (float*)smem;      // [px][65] pitch; meta+slab-buf0 dead
#pragma unroll
    for (int p = 0; p < 8; p++) {
        int px = pg * 8 + p;
#pragma unroll
        for (int j = 0; j < 8; j++) {
            unsigned long long v = acc[p][j];
            float lo = __uint_as_float((unsigned)(v & 0xffffffffull));
            float hi = __uint_as_float((unsigned)(v >> 32));
            sa[px * 65 + g * 8 + j] = lo + hi;
        }
    }
    __syncthreads();

    for (int e = tid; e < 128 * 64; e += 128) {
        int oc = e >> 7, m = e & 127;
        int h = h0 + (m >> 4), w = w0 + (m & 15);
        int gi = ((b * C_ + oc) << 14) + (h << 7) + w;
        out[gi] = x[gi] + sa[m * 65 + oc];
    }
}

// ============================================================
extern "C" void kernel_launch(void* const* d_in, const int* in_sizes, int n_in,
                              void* d_out, int out_size) {
    const float* x       = (const float*)d_in[0];
    const float* w_conv1 = (const float*)d_in[1];
    const float* g1 = (const float*)d_in[2];
    const float* b1 = (const float*)d_in[3];
    const float* m1 = (const float*)d_in[4];
    const float* v1 = (const float*)d_in[5];
    const float* w_dw = (const float*)d_in[6];
    const float* g2 = (const float*)d_in[7];
    const float* b2 = (const float*)d_in[8];
    const float* m2 = (const float*)d_in[9];
    const float* v2 = (const float*)d_in[10];
    const float* w_conv2 = (const float*)d_in[11];
    const float* g3 = (const float*)d_in[12];
    const float* b3 = (const float*)d_in[13];
    const float* m3 = (const float*)d_in[14];
    const float* v3 = (const float*)d_in[15];
    const float* w_out = (const float*)d_in[16];
    float* out = (float*)d_out;

    cudaFuncSetAttribute(k3_main, cudaFuncAttributeMaxDynamicSharedMemorySize, K3_SMEM);

    k_padT<<<PAD_BLKS + W0_BLKS, 256>>>(x, w_out);
    k1_conv1<<<PIXT / 256, 256>>>(x, w_conv1, g1, b1, m1, v1);
    k2_offsets<<<128, 256>>>(w_dw, g2, b2, m2, v2, w_conv2, g3, b3, m3, v3);
    k3_main<<<B_ * 128, 128, K3_SMEM>>>(x, out);
}

// round 13
// speedup vs baseline: 1.1527x; 1.1527x over previous
#include <cuda_runtime.h>
#include <math.h>
#include <stdint.h>

// Problem constants
#define B_  2
#define C_  64
#define H_  128
#define W_  128
#define HW_ (H_*W_)          // 16384
#define HID 16
#define OFC 18
#define NPT 9
#define KTOT (C_*NPT)        // 576
#define PIXT (B_*HW_)        // 32768
#define HP_  130
#define WP_  130
#define HWP_ (HP_*WP_)       // 16900

// ---- device scratch (no runtime allocation allowed) ----
__device__ float g_f  [B_*HID*HW_];       // offset-branch feature [B,16,H,W]
__device__ float g_off[B_*OFC*HW_];       // offsets               [B,18,H,W]
__device__ float g_wt2[288*128];          // chunk-packed w_out (see k_padT)
__device__ float g_xp [B_*HWP_*C_ + 8];   // TRANSPOSED padded input [B][130*130][64]

// packed fp32x2 FMA (per-component accumulate: pairs carry adjacent k)
#define FMA2(d,a,b) asm("fma.rn.f32x2 %0, %1, %2, %0;" : "+l"(d) : "l"(a), "l"(b))

__device__ __forceinline__ void cp_async16(uint32_t dst, const void* src) {
    asm volatile("cp.async.ca.shared.global [%0], [%1], 16;" :: "r"(dst), "l"(src));
}
#define CP_COMMIT() asm volatile("cp.async.commit_group;")
#define CP_WAIT0()  asm volatile("cp.async.wait_group 0;")

// ============================================================
// K_padT: zero-pad + TRANSPOSE x into g_xp[b][hw_p][c]
//  tail: pack w_out into g_wt2:
//   chunk c2 = n*2 + (ci>>5)  (18 chunks of 32 k; n = sample pt)
//   row R = c2*16 + ((ci&31)>>1)    (16 k-pair rows per chunk)
//   col  = g*8 + o2*2 + q           (g=oc>>2, o2=oc&3, q=ci&1)
// ============================================================
#define PAD_BLKS (B_*HP_)
#define W0_BLKS  ((KTOT*C_ + 255)/256)
__global__ __launch_bounds__(256)
void k_padT(const float* __restrict__ x, const float* __restrict__ w) {
    int blk = blockIdx.x;
    int tid = threadIdx.x;
    if (blk < PAD_BLKS) {
        __shared__ float ts[WP_ * 65];     // [w][c] pitch 65 (conflict-free)
        int b = blk / HP_, h = blk % HP_;
        if (h >= 1 && h <= H_) {
            const float* xr = x + (size_t)b * C_ * HW_ + (h - 1) * W_;
            for (int e = tid; e < C_ * W_; e += 256) {
                int c = e >> 7, w2 = e & 127;            // coalesced read along w
                ts[(w2 + 1) * 65 + c] = xr[c * HW_ + w2];
            }
            if (tid < 2 * C_) {                          // border columns
                int c = tid & 63, side = tid >> 6;
                ts[(side ? (WP_ - 1) * 65 : 0) + c] = 0.f;
            }
        } else {
            for (int e = tid; e < WP_ * C_; e += 256) {
                int w2 = e >> 6, c = e & 63;
                ts[w2 * 65 + c] = 0.f;
            }
        }
        __syncthreads();
        float* dst = g_xp + ((size_t)b * HP_ + h) * WP_ * C_;
        for (int e = tid; e < WP_ * C_; e += 256) {
            int w2 = e >> 6, c = e & 63;
            dst[e] = ts[w2 * 65 + c];                    // coalesced write along c
        }
    } else {
        int t = (blk - PAD_BLKS) * 256 + tid;
        if (t < KTOT * C_) {
            int oc = t / KTOT, r = t - oc * KTOT;        // r = ci*9 + n
            int ci = r / 9, n = r - ci * 9;
            int c2 = n * 2 + (ci >> 5);
            int R  = c2 * 16 + ((ci & 31) >> 1);
            int q  = ci & 1;
            int g  = oc >> 2, o2 = oc & 3;
            int col = g * 8 + o2 * 2 + q;
            g_wt2[R * 128 + col] = w[t];
        }
    }
}

// ============================================================
// K1: f = relu(bn(conv1x1_{64->16}(x)))
// ============================================================
__global__ void k1_conv1(const float* __restrict__ x,
                         const float* __restrict__ w1,
                         const float* __restrict__ g1,
                         const float* __restrict__ b1,
                         const float* __restrict__ m1,
                         const float* __restrict__ v1) {
    __shared__ float ws[C_][HID];
    __shared__ float inv_s[HID], beta_s[HID];
    int tid = threadIdx.x;
    for (int e = tid; e < HID * C_; e += 256) {
        int o = e / C_, c = e % C_;
        ws[c][o] = w1[e];
    }
    if (tid < HID) {
        float inv = g1[tid] * rsqrtf(v1[tid] + 1e-5f);
        inv_s[tid] = inv;
        beta_s[tid] = b1[tid] - m1[tid] * inv;
    }
    __syncthreads();

    int p = blockIdx.x * 256 + tid;
    int b = p >> 14, hw = p & (HW_ - 1);
    const float* xb = x + (size_t)b * C_ * HW_ + hw;

    float acc[HID];
#pragma unroll
    for (int o = 0; o < HID; o++) acc[o] = 0.f;
    for (int c = 0; c < C_; c++) {
        float xv = xb[c * HW_];
#pragma unroll
        for (int o = 0; o < HID; o++) acc[o] += ws[c][o] * xv;
    }
    float* fb = g_f + (size_t)b * HID * HW_ + hw;
#pragma unroll
    for (int o = 0; o < HID; o++)
        fb[o * HW_] = fmaxf(acc[o] * inv_s[o] + beta_s[o], 0.f);
}

// ============================================================
// K2 (tiled): off = relu(bn3(1x1( relu(bn2(3x3(f))) )))
// ============================================================
__global__ __launch_bounds__(256)
void k2_offsets(const float* __restrict__ wdw,
                const float* __restrict__ g2, const float* __restrict__ b2,
                const float* __restrict__ m2, const float* __restrict__ v2,
                const float* __restrict__ wc2,
                const float* __restrict__ g3, const float* __restrict__ b3,
                const float* __restrict__ m3, const float* __restrict__ v3) {
    __shared__ float fs[HID * 18 * 18];
    __shared__ float wdw_s[OFC * HID * 9];
    __shared__ float wc2_s[OFC * OFC];
    __shared__ float inv2_s[OFC], beta2_s[OFC], inv3_s[OFC], beta3_s[OFC];
    int tid = threadIdx.x;

    int blk = blockIdx.x;
    int b = blk >> 6, t = blk & 63;
    int h0 = (t >> 3) << 4, w0 = (t & 7) << 4;

    for (int e = tid; e < OFC * HID * 9; e += 256) wdw_s[e] = wdw[e];
    for (int e = tid; e < OFC * OFC; e += 256)     wc2_s[e] = wc2[e];
    if (tid < OFC) {
        float i2 = g2[tid] * rsqrtf(v2[tid] + 1e-5f);
        inv2_s[tid] = i2; beta2_s[tid] = b2[tid] - m2[tid] * i2;
        float i3 = g3[tid] * rsqrtf(v3[tid] + 1e-5f);
        inv3_s[tid] = i3; beta3_s[tid] = b3[tid] - m3[tid] * i3;
    }

    const float* fb = g_f + (size_t)b * HID * HW_;
    for (int e = tid; e < HID * 324; e += 256) {
        int ci = e / 324, r = e - ci * 324;
        int hh = r / 18, ww = r - hh * 18;
        int h = h0 - 1 + hh, w = w0 - 1 + ww;
        float v = 0.f;
        if (h >= 0 && h < H_ && w >= 0 && w < W_)
            v = fb[ci * HW_ + h * W_ + w];
        fs[e] = v;
    }
    __syncthreads();

    int ty2 = tid >> 4, tx2 = tid & 15;
    float acc[OFC];
#pragma unroll
    for (int o = 0; o < OFC; o++) acc[o] = 0.f;

    for (int ci = 0; ci < HID; ci++) {
        float fv[9];
        const float* fsc = fs + ci * 324;
#pragma unroll
        for (int dh = 0; dh < 3; dh++)
#pragma unroll
            for (int dw = 0; dw < 3; dw++)
                fv[dh * 3 + dw] = fsc[(ty2 + dh) * 18 + (tx2 + dw)];
        const float* wp = wdw_s + ci * 9;
#pragma unroll
        for (int o = 0; o < OFC; o++) {
            const float* wo = wp + o * (HID * 9);
            float a = acc[o];
#pragma unroll
            for (int k = 0; k < 9; k++) a += wo[k] * fv[k];
            acc[o] = a;
        }
    }
    float tv[OFC];
#pragma unroll
    for (int o = 0; o < OFC; o++)
        tv[o] = fmaxf(acc[o] * inv2_s[o] + beta2_s[o], 0.f);

    int h = h0 + ty2, w = w0 + tx2;
    float* op = g_off + (size_t)b * OFC * HW_ + h * W_ + w;
#pragma unroll
    for (int o2 = 0; o2 < OFC; o2++) {
        float a = 0.f;
#pragma unroll
        for (int o = 0; o < OFC; o++) a += wc2_s[o2 * OFC + o] * tv[o];
        op[o2 * HW_] = fmaxf(a * inv3_s[o2] + beta3_s[o2], 0.f);
    }
}

// ============================================================
// K3: fused bilinear sampler + SGEMM (k-paired f32x2), 8px x 4oc tiles
//   block = 256 threads, tile = 128 px x 64 oc, 18 chunks of 32 k
//   2 CTAs/SM (16 warps): smem 71.7KB, <=128 regs
// ============================================================
#define APITCH 36
#define SLABN (128*APITCH)                  // 4608 floats per slab buffer
#define SMEM_SLAB 18432
#define SMEM_B    (SMEM_SLAB + 2*SLABN*4)   // 55296
#define K3_SMEM   (SMEM_B + 2*2048*4)       // 71680

__global__ __launch_bounds__(256, 2)
void k3_main(const float* __restrict__ x, float* __restrict__ out) {
    extern __shared__ char smem[];
    float4* meta4 = (float4*)smem;                 // [128 px][9 pts], 16B each
    float*  slab  = (float*)(smem + SMEM_SLAB);    // [2][128][APITCH]
    float*  bsm   = (float*)(smem + SMEM_B);       // [2][2048]

    int tid = threadIdx.x;
    int blk = blockIdx.x;                 // 256 blocks
    int b = blk >> 7;
    int tile = blk & 127;
    int h0 = (tile >> 3) << 3;            // 16 h-tiles of 8
    int w0 = (tile & 7) << 4;             // 8 w-tiles of 16

    uint32_t bsm_u32 = (uint32_t)__cvta_generic_to_shared(bsm) + tid * 32;
#define STAGE_B(buf, cc)                                                      \
    {                                                                         \
        const float* src = g_wt2 + (cc) * 2048 + tid * 8;                     \
        uint32_t dst = bsm_u32 + (buf) * 8192;                                \
        cp_async16(dst,      src);                                            \
        cp_async16(dst + 16, src + 4);                                        \
        CP_COMMIT();                                                          \
    }

    STAGE_B(0, 0)

    // ---- compact bilinear metadata: 128 px x 9 pts, 16B each ----
    const float* offp = g_off + (size_t)b * OFC * HW_;
    for (int e = tid; e < 128 * NPT; e += 256) {
        int px = e / 9, n = e - px * 9;
        int h = h0 + (px >> 4), w = w0 + (px & 15);
        int hw = h * W_ + w;
        float offx = offp[n * HW_ + hw];
        float offy = offp[(NPT + n) * HW_ + hw];
        float pxf = (float)(h + 1) + (float)(n / 3 - 1) + offx;
        float pyf = (float)(w + 1) + (float)(n % 3 - 1) + offy;
        float flx = floorf(pxf), fly = floorf(pyf);
        float qltx = fminf(fmaxf(flx, 0.f), 129.f);
        float qlty = fminf(fmaxf(fly, 0.f), 129.f);
        float qrbx = fminf(fmaxf(flx + 1.f, 0.f), 129.f);
        float qrby = fminf(fmaxf(fly + 1.f, 0.f), 129.f);
        float pxc = fminf(fmaxf(pxf, 0.f), 129.f);
        float pyc = fminf(fmaxf(pyf, 0.f), 129.f);
        float ax = qltx - pxc;             // 0 whenever x clamps (corners equal)
        float ay = qlty - pyc;
        unsigned clampx = (qltx == qrbx) ? 0x80000000u : 0u;
        unsigned clampy = (qlty == qrby) ? 0x80000000u : 0u;
        int ltx = (int)qltx, lty = (int)qlty, rbx = (int)qrbx, rby = (int)qrby;
        unsigned i_lt = (unsigned)(ltx * WP_ + lty);
        unsigned i_rb = (unsigned)(rbx * WP_ + rby);
        unsigned i_lb = (unsigned)(ltx * WP_ + rby);
        unsigned i_rt = (unsigned)(rbx * WP_ + lty);
        unsigned u0 = i_lt | (i_rb << 16) | clampx;
        unsigned u1 = i_lb | (i_rt << 16) | clampy;
        meta4[e] = make_float4(__uint_as_float(u0), __uint_as_float(u1), ax, ay);
    }

    const float* xpb = g_xp + (size_t)b * HWP_ * C_;
    const int lane = tid & 31;
    const int wid  = tid >> 5;            // 0..7
    const int lc   = lane & 15;           // channel-pair within chunk
    const int half = lane >> 4;           // px parity within iter

    // warp-cooperative gather: warp w -> px [16w, 16w+16), 2 px per iter
#define GATHER_CHUNK(dbuf, cc)                                                \
    {                                                                         \
        int n_ = (cc) >> 1;                                                   \
        const float* xch = xpb + ((cc) & 1) * 32 + 2 * lc;                    \
        float* sd = slab + (dbuf) * SLABN + 2 * lc;                           \
        _Pragma("unroll 4")                                                   \
        for (int it = 0; it < 8; it++) {                                      \
            int px = wid * 16 + it * 2 + half;                                \
            float4 mm = meta4[px * 9 + n_];                                   \
            unsigned u0 = __float_as_uint(mm.x), u1 = __float_as_uint(mm.y);  \
            float ax = mm.z, ay = mm.w;                                       \
            float wxl = 1.f + ax, wyl = 1.f + ay;                             \
            float wxr = (u0 & 0x80000000u) ? 1.f : -ax;                       \
            float wyr = (u1 & 0x80000000u) ? 1.f : -ay;                       \
            float gx = wxl * wyl, gy = wxr * wyr;                             \
            float gz = wxl * wyr, gw = wxr * wyl;                             \
            float2 lt = *(const float2*)(xch + ((u0 & 0x7fffu) << 6));        \
            float2 rb = *(const float2*)(xch + (((u0 >> 16) & 0x7fffu) << 6));\
            float2 lb = *(const float2*)(xch + ((u1 & 0x7fffu) << 6));        \
            float2 rt = *(const float2*)(xch + (((u1 >> 16) & 0x7fffu) << 6));\
            float v0 = gx*lt.x + gy*rb.x + gz*lb.x + gw*rt.x;                 \
            float v1 = gx*lt.y + gy*rb.y + gz*lb.y + gw*rt.y;                 \
            *(float2*)(sd + px * APITCH) = make_float2(v0, v1);               \
        }                                                                     \
    }

    CP_WAIT0();
    __syncthreads();               // meta + B(0) visible
    GATHER_CHUNK(0, 0)
    __syncthreads();               // slab(0) visible

    const int g  = tid & 15;       // oc-group: oc = g*4 .. g*4+3
    const int pg = tid >> 4;       // px-group: px = pg*8 .. pg*8+7

    unsigned long long acc[8][4];  // [px][oc], f32x2 (even-k, odd-k) partials
#pragma unroll
    for (int i = 0; i < 8; i++)
#pragma unroll
        for (int j = 0; j < 4; j++) acc[i][j] = 0ull;

    // ---- pipelined chunk loop ----
    for (int c = 0; c < 18; c++) {
        if (c < 17) {
            STAGE_B((c + 1) & 1, c + 1)
            GATHER_CHUNK((c + 1) & 1, c + 1)
        }

        const float* ab = slab + (c & 1) * SLABN + pg * (8 * APITCH);
        const float* bp = bsm + (c & 1) * 2048 + g * 8;
#pragma unroll 4
        for (int kp = 0; kp < 16; kp++) {         // one k-pair (2 k) per iter
            unsigned long long a[8];
#pragma unroll
            for (int p = 0; p < 8; p++)
                a[p] = *(const unsigned long long*)(ab + p * APITCH + kp * 2);
            ulonglong2 bv = *(const ulonglong2*)(bp + kp * 128);
            ulonglong2 bw = *(const ulonglong2*)(bp + kp * 128 + 4);
#pragma unroll
            for (int p = 0; p < 8; p++) {
                FMA2(acc[p][0], a[p], bv.x);
                FMA2(acc[p][1], a[p], bv.y);
                FMA2(acc[p][2], a[p], bw.x);
                FMA2(acc[p][3], a[p], bw.y);
            }
        }

        CP_WAIT0();
        __syncthreads();           // publish slab(c+1) + B(c+1)
    }

    // ---- epilogue: fold k-partials, stage via smem, coalesced residual ----
    __syncthreads();
    float* sa = (float*)smem;      // [px][65]; meta + slab-buf0 dead
#pragma unroll
    for (int p = 0; p < 8; p++) {
        int px = pg * 8 + p;
#pragma unroll
        for (int j = 0; j < 4; j++) {
            unsigned long long v = acc[p][j];
            float lo = __uint_as_float((unsigned)(v & 0xffffffffull));
            float hi = __uint_as_float((unsigned)(v >> 32));
            sa[px * 65 + g * 4 + j] = lo + hi;
        }
    }
    __syncthreads();

    for (int e = tid; e < 128 * 64; e += 256) {
        int oc = e >> 7, m = e & 127;
        int h = h0 + (m >> 4), w = w0 + (m & 15);
        int gi = ((b * C_ + oc) << 14) + (h << 7) + w;
        out[gi] = x[gi] + sa[m * 65 + oc];
    }
}

// ============================================================
extern "C" void kernel_launch(void* const* d_in, const int* in_sizes, int n_in,
                              void* d_out, int out_size) {
    const float* x       = (const float*)d_in[0];
    const float* w_conv1 = (const float*)d_in[1];
    const float* g1 = (const float*)d_in[2];
    const float* b1 = (const float*)d_in[3];
    const float* m1 = (const float*)d_in[4];
    const float* v1 = (const float*)d_in[5];
    const float* w_dw = (const float*)d_in[6];
    const float* g2 = (const float*)d_in[7];
    const float* b2 = (const float*)d_in[8];
    const float* m2 = (const float*)d_in[9];
    const float* v2 = (const float*)d_in[10];
    const float* w_conv2 = (const float*)d_in[11];
    const float* g3 = (const float*)d_in[12];
    const float* b3 = (const float*)d_in[13];
    const float* m3 = (const float*)d_in[14];
    const float* v3 = (const float*)d_in[15];
    const float* w_out = (const float*)d_in[16];
    float* out = (float*)d_out;

    cudaFuncSetAttribute(k3_main, cudaFuncAttributeMaxDynamicSharedMemorySize, K3_SMEM);

    k_padT<<<PAD_BLKS + W0_BLKS, 256>>>(x, w_out);
    k1_conv1<<<PIXT / 256, 256>>>(x, w_conv1, g1, b1, m1, v1);
    k2_offsets<<<128, 256>>>(w_dw, g2, b2, m2, v2, w_conv2, g3, b3, m3, v3);
    k3_main<<<B_ * 128, 256, K3_SMEM>>>(x, out);
}

// round 14
// speedup vs baseline: 1.2030x; 1.0437x over previous
#include <cuda_runtime.h>
#include <math.h>
#include <stdint.h>

// Problem constants
#define B_  2
#define C_  64
#define H_  128
#define W_  128
#define HW_ (H_*W_)          // 16384
#define HID 16
#define OFC 18
#define NPT 9
#define KTOT (C_*NPT)        // 576
#define PIXT (B_*HW_)        // 32768
#define HP_  130
#define WP_  130
#define HWP_ (HP_*WP_)       // 16900

// ---- device scratch (no runtime allocation allowed) ----
__device__ float g_f  [B_*HID*HW_];       // offset-branch feature [B,16,H,W]
__device__ float g_off[B_*OFC*HW_];       // offsets               [B,18,H,W]
__device__ float g_wt2[288*192];          // chunk-packed w_out, swizzled rows
__device__ float g_xp [B_*HWP_*C_ + 8];   // TRANSPOSED padded input [B][130*130][64]

// packed fp32x2 FMA (per-component accumulate: pairs carry adjacent k)
#define FMA2(d,a,b) asm("fma.rn.f32x2 %0, %1, %2, %0;" : "+l"(d) : "l"(a), "l"(b))

__device__ __forceinline__ void cp_async16(uint32_t dst, const void* src) {
    asm volatile("cp.async.ca.shared.global [%0], [%1], 16;" :: "r"(dst), "l"(src));
}
#define CP_COMMIT() asm volatile("cp.async.commit_group;")
#define CP_WAIT0()  asm volatile("cp.async.wait_group 0;")

// ============================================================
// K_padT: zero-pad + TRANSPOSE x into g_xp[b][hw_p][c]
//  tail: pack w_out into g_wt2 (bank-conflict-free rows):
//   chunk c2 = n*2 + (ci>>5)  (18 chunks of 32 k; n = sample pt)
//   row R = c2*16 + ((ci&31)>>1)   (16 k-pair rows/chunk, pitch 192 floats)
//   col  = g*12 + o2*2 + q   (g=oc>>2, o2=oc&3, q=ci&1; 8 of 12 used)
//   -> per-warp LDS.128 lanes at 48B spacing tile all 32 banks exactly
// ============================================================
#define PAD_BLKS (B_*HP_)
#define W0_BLKS  ((KTOT*C_ + 255)/256)
__global__ __launch_bounds__(256)
void k_padT(const float* __restrict__ x, const float* __restrict__ w) {
    int blk = blockIdx.x;
    int tid = threadIdx.x;
    if (blk < PAD_BLKS) {
        __shared__ float ts[WP_ * 65];     // [w][c] pitch 65 (conflict-free)
        int b = blk / HP_, h = blk % HP_;
        if (h >= 1 && h <= H_) {
            const float* xr = x + (size_t)b * C_ * HW_ + (h - 1) * W_;
            for (int e = tid; e < C_ * W_; e += 256) {
                int c = e >> 7, w2 = e & 127;            // coalesced read along w
                ts[(w2 + 1) * 65 + c] = xr[c * HW_ + w2];
            }
            if (tid < 2 * C_) {                          // border columns
                int c = tid & 63, side = tid >> 6;
                ts[(side ? (WP_ - 1) * 65 : 0) + c] = 0.f;
            }
        } else {
            for (int e = tid; e < WP_ * C_; e += 256) {
                int w2 = e >> 6, c = e & 63;
                ts[w2 * 65 + c] = 0.f;
            }
        }
        __syncthreads();
        float* dst = g_xp + ((size_t)b * HP_ + h) * WP_ * C_;
        for (int e = tid; e < WP_ * C_; e += 256) {
            int w2 = e >> 6, c = e & 63;
            dst[e] = ts[w2 * 65 + c];                    // coalesced write along c
        }
    } else {
        int t = (blk - PAD_BLKS) * 256 + tid;
        if (t < KTOT * C_) {
            int oc = t / KTOT, r = t - oc * KTOT;        // r = ci*9 + n
            int ci = r / 9, n = r - ci * 9;
            int c2 = n * 2 + (ci >> 5);
            int R  = c2 * 16 + ((ci & 31) >> 1);
            int q  = ci & 1;
            int g  = oc >> 2, o2 = oc & 3;
            int col = g * 12 + o2 * 2 + q;
            g_wt2[R * 192 + col] = w[t];
        }
    }
}

// ============================================================
// K1: f = relu(bn(conv1x1_{64->16}(x)))
// ============================================================
__global__ void k1_conv1(const float* __restrict__ x,
                         const float* __restrict__ w1,
                         const float* __restrict__ g1,
                         const float* __restrict__ b1,
                         const float* __restrict__ m1,
                         const float* __restrict__ v1) {
    __shared__ float ws[C_][HID];
    __shared__ float inv_s[HID], beta_s[HID];
    int tid = threadIdx.x;
    for (int e = tid; e < HID * C_; e += 256) {
        int o = e / C_, c = e % C_;
        ws[c][o] = w1[e];
    }
    if (tid < HID) {
        float inv = g1[tid] * rsqrtf(v1[tid] + 1e-5f);
        inv_s[tid] = inv;
        beta_s[tid] = b1[tid] - m1[tid] * inv;
    }
    __syncthreads();

    int p = blockIdx.x * 256 + tid;
    int b = p >> 14, hw = p & (HW_ - 1);
    const float* xb = x + (size_t)b * C_ * HW_ + hw;

    float acc[HID];
#pragma unroll
    for (int o = 0; o < HID; o++) acc[o] = 0.f;
    for (int c = 0; c < C_; c++) {
        float xv = xb[c * HW_];
#pragma unroll
        for (int o = 0; o < HID; o++) acc[o] += ws[c][o] * xv;
    }
    float* fb = g_f + (size_t)b * HID * HW_ + hw;
#pragma unroll
    for (int o = 0; o < HID; o++)
        fb[o * HW_] = fmaxf(acc[o] * inv_s[o] + beta_s[o], 0.f);
}

// ============================================================
// K2 (tiled): off = relu(bn3(1x1( relu(bn2(3x3(f))) )))
// ============================================================
__global__ __launch_bounds__(256)
void k2_offsets(const float* __restrict__ wdw,
                const float* __restrict__ g2, const float* __restrict__ b2,
                const float* __restrict__ m2, const float* __restrict__ v2,
                const float* __restrict__ wc2,
                const float* __restrict__ g3, const float* __restrict__ b3,
                const float* __restrict__ m3, const float* __restrict__ v3) {
    __shared__ float fs[HID * 18 * 18];
    __shared__ float wdw_s[OFC * HID * 9];
    __shared__ float wc2_s[OFC * OFC];
    __shared__ float inv2_s[OFC], beta2_s[OFC], inv3_s[OFC], beta3_s[OFC];
    int tid = threadIdx.x;

    int blk = blockIdx.x;
    int b = blk >> 6, t = blk & 63;
    int h0 = (t >> 3) << 4, w0 = (t & 7) << 4;

    for (int e = tid; e < OFC * HID * 9; e += 256) wdw_s[e] = wdw[e];
    for (int e = tid; e < OFC * OFC; e += 256)     wc2_s[e] = wc2[e];
    if (tid < OFC) {
        float i2 = g2[tid] * rsqrtf(v2[tid] + 1e-5f);
        inv2_s[tid] = i2; beta2_s[tid] = b2[tid] - m2[tid] * i2;
        float i3 = g3[tid] * rsqrtf(v3[tid] + 1e-5f);
        inv3_s[tid] = i3; beta3_s[tid] = b3[tid] - m3[tid] * i3;
    }

    const float* fb = g_f + (size_t)b * HID * HW_;
    for (int e = tid; e < HID * 324; e += 256) {
        int ci = e / 324, r = e - ci * 324;
        int hh = r / 18, ww = r - hh * 18;
        int h = h0 - 1 + hh, w = w0 - 1 + ww;
        float v = 0.f;
        if (h >= 0 && h < H_ && w >= 0 && w < W_)
            v = fb[ci * HW_ + h * W_ + w];
        fs[e] = v;
    }
    __syncthreads();

    int ty2 = tid >> 4, tx2 = tid & 15;
    float acc[OFC];
#pragma unroll
    for (int o = 0; o < OFC; o++) acc[o] = 0.f;

    for (int ci = 0; ci < HID; ci++) {
        float fv[9];
        const float* fsc = fs + ci * 324;
#pragma unroll
        for (int dh = 0; dh < 3; dh++)
#pragma unroll
            for (int dw = 0; dw < 3; dw++)
                fv[dh * 3 + dw] = fsc[(ty2 + dh) * 18 + (tx2 + dw)];
        const float* wp = wdw_s + ci * 9;
#pragma unroll
        for (int o = 0; o < OFC; o++) {
            const float* wo = wp + o * (HID * 9);
            float a = acc[o];
#pragma unroll
            for (int k = 0; k < 9; k++) a += wo[k] * fv[k];
            acc[o] = a;
        }
    }
    float tv[OFC];
#pragma unroll
    for (int o = 0; o < OFC; o++)
        tv[o] = fmaxf(acc[o] * inv2_s[o] + beta2_s[o], 0.f);

    int h = h0 + ty2, w = w0 + tx2;
    float* op = g_off + (size_t)b * OFC * HW_ + h * W_ + w;
#pragma unroll
    for (int o2 = 0; o2 < OFC; o2++) {
        float a = 0.f;
#pragma unroll
        for (int o = 0; o < OFC; o++) a += wc2_s[o2 * OFC + o] * tv[o];
        op[o2 * HW_] = fmaxf(a * inv3_s[o2] + beta3_s[o2], 0.f);
    }
}

// ============================================================
// K3: fused bilinear sampler + SGEMM (k-paired f32x2), 8px x 4oc tiles
//   bank-conflict-free B (48B group spacing), LDS.128 A over 2 k-pairs
//   block = 256 threads, tile = 128 px x 64 oc, 18 chunks of 32 k
// ============================================================
#define APITCH 36
#define SLABN (128*APITCH)                  // 4608 floats per slab buffer
#define BCH   3072                          // floats per B chunk (16 kp x 192)
#define SMEM_SLAB 18432
#define SMEM_B    (SMEM_SLAB + 2*SLABN*4)   // 55296
#define K3_SMEM   (SMEM_B + 2*BCH*4)        // 79872

__global__ __launch_bounds__(256, 2)
void k3_main(const float* __restrict__ x, float* __restrict__ out) {
    extern __shared__ char smem[];
    float4* meta4 = (float4*)smem;                 // [128 px][9 pts], 16B each
    float*  slab  = (float*)(smem + SMEM_SLAB);    // [2][128][APITCH]
    float*  bsm   = (float*)(smem + SMEM_B);       // [2][BCH]

    int tid = threadIdx.x;
    int blk = blockIdx.x;                 // 256 blocks
    int b = blk >> 7;
    int tile = blk & 127;
    int h0 = (tile >> 3) << 3;            // 16 h-tiles of 8
    int w0 = (tile & 7) << 4;             // 8 w-tiles of 16

    // B staging: 12288 B per chunk, 3 x 16B per thread (coalesced)
    uint32_t bsm_u32 = (uint32_t)__cvta_generic_to_shared(bsm) + tid * 48;
#define STAGE_B(buf, cc)                                                      \
    {                                                                         \
        const float* src = g_wt2 + (cc) * BCH + tid * 12;                     \
        uint32_t dst = bsm_u32 + (buf) * (BCH*4);                             \
        cp_async16(dst,      src);                                            \
        cp_async16(dst + 16, src + 4);                                        \
        cp_async16(dst + 32, src + 8);                                        \
        CP_COMMIT();                                                          \
    }

    STAGE_B(0, 0)

    // ---- compact bilinear metadata: 128 px x 9 pts, 16B each ----
    const float* offp = g_off + (size_t)b * OFC * HW_;
    for (int e = tid; e < 128 * NPT; e += 256) {
        int px = e / 9, n = e - px * 9;
        int h = h0 + (px >> 4), w = w0 + (px & 15);
        int hw = h * W_ + w;
        float offx = offp[n * HW_ + hw];
        float offy = offp[(NPT + n) * HW_ + hw];
        float pxf = (float)(h + 1) + (float)(n / 3 - 1) + offx;
        float pyf = (float)(w + 1) + (float)(n % 3 - 1) + offy;
        float flx = floorf(pxf), fly = floorf(pyf);
        float qltx = fminf(fmaxf(flx, 0.f), 129.f);
        float qlty = fminf(fmaxf(fly, 0.f), 129.f);
        float qrbx = fminf(fmaxf(flx + 1.f, 0.f), 129.f);
        float qrby = fminf(fmaxf(fly + 1.f, 0.f), 129.f);
        float pxc = fminf(fmaxf(pxf, 0.f), 129.f);
        float pyc = fminf(fmaxf(pyf, 0.f), 129.f);
        float ax = qltx - pxc;             // 0 whenever x clamps (corners equal)
        float ay = qlty - pyc;
        unsigned clampx = (qltx == qrbx) ? 0x80000000u : 0u;
        unsigned clampy = (qlty == qrby) ? 0x80000000u : 0u;
        int ltx = (int)qltx, lty = (int)qlty, rbx = (int)qrbx, rby = (int)qrby;
        unsigned i_lt = (unsigned)(ltx * WP_ + lty);
        unsigned i_rb = (unsigned)(rbx * WP_ + rby);
        unsigned i_lb = (unsigned)(ltx * WP_ + rby);
        unsigned i_rt = (unsigned)(rbx * WP_ + lty);
        unsigned u0 = i_lt | (i_rb << 16) | clampx;
        unsigned u1 = i_lb | (i_rt << 16) | clampy;
        meta4[e] = make_float4(__uint_as_float(u0), __uint_as_float(u1), ax, ay);
    }

    const float* xpb = g_xp + (size_t)b * HWP_ * C_;
    const int lane = tid & 31;
    const int wid  = tid >> 5;            // 0..7
    const int lc   = lane & 15;           // channel-pair within chunk
    const int half = lane >> 4;           // px parity within iter

    // warp-cooperative gather: warp w -> px [16w, 16w+16), 2 px per iter
#define GATHER_CHUNK(dbuf, cc)                                                \
    {                                                                         \
        int n_ = (cc) >> 1;                                                   \
        const float* xch = xpb + ((cc) & 1) * 32 + 2 * lc;                    \
        float* sd = slab + (dbuf) * SLABN + 2 * lc;                           \
        _Pragma("unroll 4")                                                   \
        for (int it = 0; it < 8; it++) {                                      \
            int px = wid * 16 + it * 2 + half;                                \
            float4 mm = meta4[px * 9 + n_];                                   \
            unsigned u0 = __float_as_uint(mm.x), u1 = __float_as_uint(mm.y);  \
            float ax = mm.z, ay = mm.w;                                       \
            float wxl = 1.f + ax, wyl = 1.f + ay;                             \
            float wxr = (u0 & 0x80000000u) ? 1.f : -ax;                       \
            float wyr = (u1 & 0x80000000u) ? 1.f : -ay;                       \
            float gx = wxl * wyl, gy = wxr * wyr;                             \
            float gz = wxl * wyr, gw = wxr * wyl;                             \
            float2 lt = *(const float2*)(xch + ((u0 & 0x7fffu) << 6));        \
            float2 rb = *(const float2*)(xch + (((u0 >> 16) & 0x7fffu) << 6));\
            float2 lb = *(const float2*)(xch + ((u1 & 0x7fffu) << 6));        \
            float2 rt = *(const float2*)(xch + (((u1 >> 16) & 0x7fffu) << 6));\
            float v0 = gx*lt.x + gy*rb.x + gz*lb.x + gw*rt.x;                 \
            float v1 = gx*lt.y + gy*rb.y + gz*lb.y + gw*rt.y;                 \
            *(float2*)(sd + px * APITCH) = make_float2(v0, v1);               \
        }                                                                     \
    }

    CP_WAIT0();
    __syncthreads();               // meta + B(0) visible
    GATHER_CHUNK(0, 0)
    __syncthreads();               // slab(0) visible

    const int g  = tid & 15;       // oc-group: oc = g*4 .. g*4+3
    const int pg = tid >> 4;       // px-group: px = pg*8 .. pg*8+7

    unsigned long long acc[8][4];  // [px][oc], f32x2 (even-k, odd-k) partials
#pragma unroll
    for (int i = 0; i < 8; i++)
#pragma unroll
        for (int j = 0; j < 4; j++) acc[i][j] = 0ull;

    // ---- pipelined chunk loop ----
    for (int c = 0; c < 18; c++) {
        if (c < 17) {
            STAGE_B((c + 1) & 1, c + 1)
            GATHER_CHUNK((c + 1) & 1, c + 1)
        }

        const float* ab = slab + (c & 1) * SLABN + pg * (8 * APITCH);
        const float* bp = bsm + (c & 1) * BCH + g * 12;
#pragma unroll
        for (int dk = 0; dk < 8; dk++) {          // 2 k-pairs (4 k) per iter
            ulonglong2 av[8];
#pragma unroll
            for (int p = 0; p < 8; p++)
                av[p] = *(const ulonglong2*)(ab + p * APITCH + dk * 4);
#pragma unroll
            for (int h2 = 0; h2 < 2; h2++) {
                const float* row = bp + (dk * 2 + h2) * 192;
                ulonglong2 bv = *(const ulonglong2*)(row);       // oc j0,j1
                ulonglong2 bw = *(const ulonglong2*)(row + 4);   // oc j2,j3
#pragma unroll
                for (int p = 0; p < 8; p++) {
                    unsigned long long a = h2 ? av[p].y : av[p].x;
                    FMA2(acc[p][0], a, bv.x);
                    FMA2(acc[p][1], a, bv.y);
                    FMA2(acc[p][2], a, bw.x);
                    FMA2(acc[p][3], a, bw.y);
                }
            }
        }

        CP_WAIT0();
        __syncthreads();           // publish slab(c+1) + B(c+1)
    }

    // ---- epilogue: fold k-partials, stage via smem, coalesced residual ----
    __syncthreads();
    float* sa = (float*)smem;      // [px][65]; meta + slab-buf0 dead
#pragma unroll
    for (int p = 0; p < 8; p++) {
        int px = pg * 8 + p;
#pragma unroll
        for (int j = 0; j < 4; j++) {
            unsigned long long v = acc[p][j];
            float lo = __uint_as_float((unsigned)(v & 0xffffffffull));
            float hi = __uint_as_float((unsigned)(v >> 32));
            sa[px * 65 + g * 4 + j] = lo + hi;
        }
    }
    __syncthreads();

    for (int e = tid; e < 128 * 64; e += 256) {
        int oc = e >> 7, m = e & 127;
        int h = h0 + (m >> 4), w = w0 + (m & 15);
        int gi = ((b * C_ + oc) << 14) + (h << 7) + w;
        out[gi] = x[gi] + sa[m * 65 + oc];
    }
}

// ============================================================
extern "C" void kernel_launch(void* const* d_in, const int* in_sizes, int n_in,
                              void* d_out, int out_size) {
    const float* x       = (const float*)d_in[0];
    const float* w_conv1 = (const float*)d_in[1];
    const float* g1 = (const float*)d_in[2];
    const float* b1 = (const float*)d_in[3];
    const float* m1 = (const float*)d_in[4];
    const float* v1 = (const float*)d_in[5];
    const float* w_dw = (const float*)d_in[6];
    const float* g2 = (const float*)d_in[7];
    const float* b2 = (const float*)d_in[8];
    const float* m2 = (const float*)d_in[9];
    const float* v2 = (const float*)d_in[10];
    const float* w_conv2 = (const float*)d_in[11];
    const float* g3 = (const float*)d_in[12];
    const float* b3 = (const float*)d_in[13];
    const float* m3 = (const float*)d_in[14];
    const float* v3 = (const float*)d_in[15];
    const float* w_out = (const float*)d_in[16];
    float* out = (float*)d_out;

    cudaFuncSetAttribute(k3_main, cudaFuncAttributeMaxDynamicSharedMemorySize, K3_SMEM);

    k_padT<<<PAD_BLKS + W0_BLKS, 256>>>(x, w_out);
    k1_conv1<<<PIXT / 256, 256>>>(x, w_conv1, g1, b1, m1, v1);
    k2_offsets<<<128, 256>>>(w_dw, g2, b2, m2, v2, w_conv2, g3, b3, m3, v3);
    k3_main<<<B_ * 128, 256, K3_SMEM>>>(x, out);
}

// round 16
// speedup vs baseline: 1.2132x; 1.0084x over previous
#include <cuda_runtime.h>
#include <math.h>
#include <stdint.h>

// Problem constants
#define B_  2
#define C_  64
#define H_  128
#define W_  128
#define HW_ (H_*W_)          // 16384
#define HID 16
#define OFC 18
#define NPT 9
#define KTOT (C_*NPT)        // 576
#define PIXT (B_*HW_)        // 32768
#define HP_  130
#define WP_  130
#define HWP_ (HP_*WP_)       // 16900

// ---- device scratch (no runtime allocation allowed) ----
__device__ float g_f  [B_*HID*HW_];       // offset-branch feature [B,16,H,W]
__device__ float g_off[B_*OFC*HW_];       // offsets               [B,18,H,W]
__device__ float g_wt2[288*192];          // chunk-packed w_out, swizzled rows
__device__ float g_xp [B_*HWP_*C_ + 8];   // TRANSPOSED padded input [B][130*130][64]

// packed fp32x2 FMA (per-component accumulate: pairs carry adjacent k)
#define FMA2(d,a,b) asm("fma.rn.f32x2 %0, %1, %2, %0;" : "+l"(d) : "l"(a), "l"(b))

__device__ __forceinline__ void cp_async16(uint32_t dst, const void* src) {
    asm volatile("cp.async.ca.shared.global [%0], [%1], 16;" :: "r"(dst), "l"(src));
}
#define CP_COMMIT() asm volatile("cp.async.commit_group;")
#define CP_WAIT0()  asm volatile("cp.async.wait_group 0;")

// ============================================================
// K_padT (fused): zero-pad+transpose x  |  pack w_out  |  k1 conv1x1
//  w_out pack (bank-conflict-free rows):
//   chunk c2 = n*2 + (ci>>5); row R = c2*16 + ((ci&31)>>1), pitch 192
//   col  = g*12 + o2*2 + q   (g=oc>>2, o2=oc&3, q=ci&1)
// ============================================================
#define PAD_BLKS (B_*HP_)
#define W0_BLKS  ((KTOT*C_ + 255)/256)
#define K1_BLKS  (PIXT/256)
__global__ __launch_bounds__(256)
void k_padT(const float* __restrict__ x, const float* __restrict__ w,
            const float* __restrict__ w1,
            const float* __restrict__ g1, const float* __restrict__ b1,
            const float* __restrict__ m1, const float* __restrict__ v1) {
    int blk = blockIdx.x;
    int tid = threadIdx.x;
    if (blk < PAD_BLKS) {
        __shared__ float ts[WP_ * 65];     // [w][c] pitch 65 (conflict-free)
        int b = blk / HP_, h = blk % HP_;
        if (h >= 1 && h <= H_) {
            const float* xr = x + (size_t)b * C_ * HW_ + (h - 1) * W_;
            for (int e = tid; e < C_ * W_; e += 256) {
                int c = e >> 7, w2 = e & 127;            // coalesced read along w
                ts[(w2 + 1) * 65 + c] = xr[c * HW_ + w2];
            }
            if (tid < 2 * C_) {                          // border columns
                int c = tid & 63, side = tid >> 6;
                ts[(side ? (WP_ - 1) * 65 : 0) + c] = 0.f;
            }
        } else {
            for (int e = tid; e < WP_ * C_; e += 256) {
                int w2 = e >> 6, c = e & 63;
                ts[w2 * 65 + c] = 0.f;
            }
        }
        __syncthreads();
        float* dst = g_xp + ((size_t)b * HP_ + h) * WP_ * C_;
        for (int e = tid; e < WP_ * C_; e += 256) {
            int w2 = e >> 6, c = e & 63;
            dst[e] = ts[w2 * 65 + c];                    // coalesced write along c
        }
    } else if (blk < PAD_BLKS + W0_BLKS) {
        int t = (blk - PAD_BLKS) * 256 + tid;
        if (t < KTOT * C_) {
            int oc = t / KTOT, r = t - oc * KTOT;        // r = ci*9 + n
            int ci = r / 9, n = r - ci * 9;
            int c2 = n * 2 + (ci >> 5);
            int R  = c2 * 16 + ((ci & 31) >> 1);
            int q  = ci & 1;
            int g  = oc >> 2, o2 = oc & 3;
            int col = g * 12 + o2 * 2 + q;
            g_wt2[R * 192 + col] = w[t];
        }
    } else {
        // ---- k1: f = relu(bn(conv1x1_{64->16}(x))) ----
        __shared__ float ws[C_][HID];
        __shared__ float inv_s[HID], beta_s[HID];
        for (int e = tid; e < HID * C_; e += 256) {
            int o = e / C_, c = e % C_;
            ws[c][o] = w1[e];
        }
        if (tid < HID) {
            float inv = g1[tid] * rsqrtf(v1[tid] + 1e-5f);
            inv_s[tid] = inv;
            beta_s[tid] = b1[tid] - m1[tid] * inv;
        }
        __syncthreads();

        int p = (blk - PAD_BLKS - W0_BLKS) * 256 + tid;
        int b = p >> 14, hw = p & (HW_ - 1);
        const float* xb = x + (size_t)b * C_ * HW_ + hw;

        float acc[HID];
#pragma unroll
        for (int o = 0; o < HID; o++) acc[o] = 0.f;
        for (int c = 0; c < C_; c++) {
            float xv = xb[c * HW_];
#pragma unroll
            for (int o = 0; o < HID; o++) acc[o] += ws[c][o] * xv;
        }
        float* fb = g_f + (size_t)b * HID * HW_ + hw;
#pragma unroll
        for (int o = 0; o < HID; o++)
            fb[o * HW_] = fmaxf(acc[o] * inv_s[o] + beta_s[o], 0.f);
    }
}

// ============================================================
// K2 (tiled): off = relu(bn3(1x1( relu(bn2(3x3(f))) )))
// ============================================================
__global__ __launch_bounds__(256)
void k2_offsets(const float* __restrict__ wdw,
                const float* __restrict__ g2, const float* __restrict__ b2,
                const float* __restrict__ m2, const float* __restrict__ v2,
                const float* __restrict__ wc2,
                const float* __restrict__ g3, const float* __restrict__ b3,
                const float* __restrict__ m3, const float* __restrict__ v3) {
    __shared__ float fs[HID * 18 * 18];
    __shared__ float wdw_s[OFC * HID * 9];
    __shared__ float wc2_s[OFC * OFC];
    __shared__ float inv2_s[OFC], beta2_s[OFC], inv3_s[OFC], beta3_s[OFC];
    int tid = threadIdx.x;

    int blk = blockIdx.x;
    int b = blk >> 6, t = blk & 63;
    int h0 = (t >> 3) << 4, w0 = (t & 7) << 4;

    for (int e = tid; e < OFC * HID * 9; e += 256) wdw_s[e] = wdw[e];
    for (int e = tid; e < OFC * OFC; e += 256)     wc2_s[e] = wc2[e];
    if (tid < OFC) {
        float i2 = g2[tid] * rsqrtf(v2[tid] + 1e-5f);
        inv2_s[tid] = i2; beta2_s[tid] = b2[tid] - m2[tid] * i2;
        float i3 = g3[tid] * rsqrtf(v3[tid] + 1e-5f);
        inv3_s[tid] = i3; beta3_s[tid] = b3[tid] - m3[tid] * i3;
    }

    const float* fb = g_f + (size_t)b * HID * HW_;
    for (int e = tid; e < HID * 324; e += 256) {
        int ci = e / 324, r = e - ci * 324;
        int hh = r / 18, ww = r - hh * 18;
        int h = h0 - 1 + hh, w = w0 - 1 + ww;
        float v = 0.f;
        if (h >= 0 && h < H_ && w >= 0 && w < W_)
            v = fb[ci * HW_ + h * W_ + w];
        fs[e] = v;
    }
    __syncthreads();

    int ty2 = tid >> 4, tx2 = tid & 15;
    float acc[OFC];
#pragma unroll
    for (int o = 0; o < OFC; o++) acc[o] = 0.f;

    for (int ci = 0; ci < HID; ci++) {
        float fv[9];
        const float* fsc = fs + ci * 324;
#pragma unroll
        for (int dh = 0; dh < 3; dh++)
#pragma unroll
            for (int dw = 0; dw < 3; dw++)
                fv[dh * 3 + dw] = fsc[(ty2 + dh) * 18 + (tx2 + dw)];
        const float* wp = wdw_s + ci * 9;
#pragma unroll
        for (int o = 0; o < OFC; o++) {
            const float* wo = wp + o * (HID * 9);
            float a = acc[o];
#pragma unroll
            for (int k = 0; k < 9; k++) a += wo[k] * fv[k];
            acc[o] = a;
        }
    }
    float tv[OFC];
#pragma unroll
    for (int o = 0; o < OFC; o++)
        tv[o] = fmaxf(acc[o] * inv2_s[o] + beta2_s[o], 0.f);

    int h = h0 + ty2, w = w0 + tx2;
    float* op = g_off + (size_t)b * OFC * HW_ + h * W_ + w;
#pragma unroll
    for (int o2 = 0; o2 < OFC; o2++) {
        float a = 0.f;
#pragma unroll
        for (int o = 0; o < OFC; o++) a += wc2_s[o2 * OFC + o] * tv[o];
        op[o2 * HW_] = fmaxf(a * inv3_s[o2] + beta3_s[o2], 0.f);
    }
}

// ============================================================
// K3: fused bilinear sampler + SGEMM (k-paired f32x2), 8px x 4oc tiles
//   FULL meta precompute: idx4 (pre-scaled) + wgt4 (final weights), 32B/sample
//   bank-conflict-free B (48B group spacing); smem 96KB -> 2 CTAs/SM
// ============================================================
#define APITCH 36
#define SLABN (128*APITCH)                  // 4608 floats per slab buffer
#define BCH   3072                          // floats per B chunk (16 kp x 192)
#define SMEM_WGT  18432                     // wgt4 after idx4 (1152 x 16B each)
#define SMEM_SLAB 36864
#define SMEM_B    (SMEM_SLAB + 2*SLABN*4)   // 73728
#define K3_SMEM   (SMEM_B + 2*BCH*4)        // 98304

__global__ __launch_bounds__(256, 2)
void k3_main(const float* __restrict__ x, float* __restrict__ out) {
    extern __shared__ char smem[];
    int4*   idx_s = (int4*)smem;                   // [128 px][9 pts]
    float4* wgt_s = (float4*)(smem + SMEM_WGT);    // [128 px][9 pts]
    float*  slab  = (float*)(smem + SMEM_SLAB);    // [2][128][APITCH]
    float*  bsm   = (float*)(smem + SMEM_B);       // [2][BCH]

    int tid = threadIdx.x;
    int blk = blockIdx.x;                 // 256 blocks
    int b = blk >> 7;
    int tile = blk & 127;
    int h0 = (tile >> 3) << 3;            // 16 h-tiles of 8
    int w0 = (tile & 7) << 4;             // 8 w-tiles of 16

    // B staging: 12288 B per chunk, 3 x 16B per thread (coalesced)
    uint32_t bsm_u32 = (uint32_t)__cvta_generic_to_shared(bsm) + tid * 48;
#define STAGE_B(buf, cc)                                                      \
    {                                                                         \
        const float* src = g_wt2 + (cc) * BCH + tid * 12;                     \
        uint32_t dst = bsm_u32 + (buf) * (BCH*4);                             \
        cp_async16(dst,      src);                                            \
        cp_async16(dst + 16, src + 4);                                        \
        cp_async16(dst + 32, src + 8);                                        \
        CP_COMMIT();                                                          \
    }

    STAGE_B(0, 0)

    // ---- full bilinear metadata: indices (pre-scaled) + final weights ----
    const float* offp = g_off + (size_t)b * OFC * HW_;
    for (int e = tid; e < 128 * NPT; e += 256) {
        int px = e / 9, n = e - px * 9;
        int h = h0 + (px >> 4), w = w0 + (px & 15);
        int hw = h * W_ + w;
        float offx = offp[n * HW_ + hw];
        float offy = offp[(NPT + n) * HW_ + hw];
        float pxf = (float)(h + 1) + (float)(n / 3 - 1) + offx;
        float pyf = (float)(w + 1) + (float)(n % 3 - 1) + offy;
        float flx = floorf(pxf), fly = floorf(pyf);
        float qltx = fminf(fmaxf(flx, 0.f), 129.f);
        float qlty = fminf(fmaxf(fly, 0.f), 129.f);
        float qrbx = fminf(fmaxf(flx + 1.f, 0.f), 129.f);
        float qrby = fminf(fmaxf(fly + 1.f, 0.f), 129.f);
        float pxc = fminf(fmaxf(pxf, 0.f), 129.f);
        float pyc = fminf(fmaxf(pyf, 0.f), 129.f);
        float gxl = 1.f + qltx - pxc, gxr = 1.f - qrbx + pxc;
        float gyl = 1.f + qlty - pyc, gyr = 1.f - qrby + pyc;
        float4 g;
        g.x = gxl * gyl; g.y = gxr * gyr; g.z = gxl * gyr; g.w = gxr * gyl;
        int ltx = (int)qltx, lty = (int)qlty, rbx = (int)qrbx, rby = (int)qrby;
        int4 id;
        id.x = (ltx * WP_ + lty) << 6;    // pre-scaled by C_=64 floats
        id.y = (rbx * WP_ + rby) << 6;
        id.z = (ltx * WP_ + rby) << 6;
        id.w = (rbx * WP_ + lty) << 6;
        idx_s[e] = id;
        wgt_s[e] = g;
    }

    const float* xpb = g_xp + (size_t)b * HWP_ * C_;
    const int lane = tid & 31;
    const int wid  = tid >> 5;            // 0..7
    const int lc   = lane & 15;           // channel-pair within chunk
    const int half = lane >> 4;           // px parity within iter

    // warp-cooperative gather: warp w -> px [16w, 16w+16), 2 px per iter
#define GATHER_CHUNK(dbuf, cc)                                                \
    {                                                                         \
        int n_ = (cc) >> 1;                                                   \
        const float* xch = xpb + ((cc) & 1) * 32 + 2 * lc;                    \
        float* sd = slab + (dbuf) * SLABN + 2 * lc;                           \
        _Pragma("unroll 4")                                                   \
        for (int it = 0; it < 8; it++) {                                      \
            int s = (wid * 16 + it * 2 + half) * 9 + n_;                      \
            int4 id = idx_s[s];                                               \
            float4 g = wgt_s[s];                                              \
            float2 lt = *(const float2*)(xch + id.x);                         \
            float2 rb = *(const float2*)(xch + id.y);                         \
            float2 lb = *(const float2*)(xch + id.z);                         \
            float2 rt = *(const float2*)(xch + id.w);                         \
            float v0 = g.x*lt.x + g.y*rb.x + g.z*lb.x + g.w*rt.x;             \
            float v1 = g.x*lt.y + g.y*rb.y + g.z*lb.y + g.w*rt.y;             \
            *(float2*)(sd + (wid * 16 + it * 2 + half) * APITCH) =            \
                make_float2(v0, v1);                                          \
        }                                                                     \
    }

    CP_WAIT0();
    __syncthreads();               // meta + B(0) visible
    GATHER_CHUNK(0, 0)
    __syncthreads();               // slab(0) visible

    const int g  = tid & 15;       // oc-group: oc = g*4 .. g*4+3
    const int pg = tid >> 4;       // px-group: px = pg*8 .. pg*8+7

    unsigned long long acc[8][4];  // [px][oc], f32x2 (even-k, odd-k) partials
#pragma unroll
    for (int i = 0; i < 8; i++)
#pragma unroll
        for (int j = 0; j < 4; j++) acc[i][j] = 0ull;

    // ---- pipelined chunk loop ----
    for (int c = 0; c < 18; c++) {
        if (c < 17) {
            STAGE_B((c + 1) & 1, c + 1)
            GATHER_CHUNK((c + 1) & 1, c + 1)
        }

        const float* ab = slab + (c & 1) * SLABN + pg * (8 * APITCH);
        const float* bp = bsm + (c & 1) * BCH + g * 12;
#pragma unroll
        for (int dk = 0; dk < 8; dk++) {          // 2 k-pairs (4 k) per iter
            ulonglong2 av[8];
#pragma unroll
            for (int p = 0; p < 8; p++)
                av[p] = *(const ulonglong2*)(ab + p * APITCH + dk * 4);
#pragma unroll
            for (int h2 = 0; h2 < 2; h2++) {
                const float* row = bp + (dk * 2 + h2) * 192;
                ulonglong2 bv = *(const ulonglong2*)(row);       // oc j0,j1
                ulonglong2 bw = *(const ulonglong2*)(row + 4);   // oc j2,j3
#pragma unroll
                for (int p = 0; p < 8; p++) {
                    unsigned long long a = h2 ? av[p].y : av[p].x;
                    FMA2(acc[p][0], a, bv.x);
                    FMA2(acc[p][1], a, bv.y);
                    FMA2(acc[p][2], a, bw.x);
                    FMA2(acc[p][3], a, bw.y);
                }
            }
        }

        CP_WAIT0();
        __syncthreads();           // publish slab(c+1) + B(c+1)
    }

    // ---- epilogue: fold k-partials, stage via smem, coalesced residual ----
    __syncthreads();
    float* sa = (float*)smem;      // [px][65]; meta dead after last gather
#pragma unroll
    for (int p = 0; p < 8; p++) {
        int px = pg * 8 + p;
#pragma unroll
        for (int j = 0; j < 4; j++) {
            unsigned long long v = acc[p][j];
            float lo = __uint_as_float((unsigned)(v & 0xffffffffull));
            float hi = __uint_as_float((unsigned)(v >> 32));
            sa[px * 65 + g * 4 + j] = lo + hi;
        }
    }
    __syncthreads();

    for (int e = tid; e < 128 * 64; e += 256) {
        int oc = e >> 7, m = e & 127;
        int h = h0 + (m >> 4), w = w0 + (m & 15);
        int gi = ((b * C_ + oc) << 14) + (h << 7) + w;
        out[gi] = x[gi] + sa[m * 65 + oc];
    }
}

// ============================================================
extern "C" void kernel_launch(void* const* d_in, const int* in_sizes, int n_in,
                              void* d_out, int out_size) {
    const float* x       = (const float*)d_in[0];
    const float* w_conv1 = (const float*)d_in[1];
    const float* g1 = (const float*)d_in[2];
    const float* b1 = (const float*)d_in[3];
    const float* m1 = (const float*)d_in[4];
    const float* v1 = (const float*)d_in[5];
    const float* w_dw = (const float*)d_in[6];
    const float* g2 = (const float*)d_in[7];
    const float* b2 = (const float*)d_in[8];
    const float* m2 = (const float*)d_in[9];
    const float* v2 = (const float*)d_in[10];
    const float* w_conv2 = (const float*)d_in[11];
    const float* g3 = (const float*)d_in[12];
    const float* b3 = (const float*)d_in[13];
    const float* m3 = (const float*)d_in[14];
    const float* v3 = (const float*)d_in[15];
    const float* w_out = (const float*)d_in[16];
    float* out = (float*)d_out;

    cudaFuncSetAttribute(k3_main, cudaFuncAttributeMaxDynamicSharedMemorySize, K3_SMEM);

    k_padT<<<PAD_BLKS + W0_BLKS + K1_BLKS, 256>>>(x, w_out, w_conv1, g1, b1, m1, v1);
    k2_offsets<<<128, 256>>>(w_dw, g2, b2, m2, v2, w_conv2, g3, b3, m3, v3);
    k3_main<<<B_ * 128, 256, K3_SMEM>>>(x, out);
}

// round 17
// speedup vs baseline: 1.3218x; 1.0895x over previous
#include <cuda_runtime.h>
#include <math.h>
#include <stdint.h>

// Problem constants
#define B_  2
#define C_  64
#define H_  128
#define W_  128
#define HW_ (H_*W_)          // 16384
#define HID 16
#define OFC 18
#define NPT 9
#define KTOT (C_*NPT)        // 576
#define PIXT (B_*HW_)        // 32768
#define HP_  130
#define WP_  130
#define HWP_ (HP_*WP_)       // 16900

// ---- device scratch (no runtime allocation allowed) ----
__device__ float g_off[B_*OFC*HW_];       // offsets               [B,18,H,W]
__device__ float g_wt2[288*192];          // chunk-packed w_out, swizzled rows
__device__ float g_xp [B_*HWP_*C_ + 8];   // TRANSPOSED padded input [B][130*130][64]

// packed fp32x2 FMA (per-component accumulate: pairs carry adjacent k)
#define FMA2(d,a,b) asm("fma.rn.f32x2 %0, %1, %2, %0;" : "+l"(d) : "l"(a), "l"(b))

__device__ __forceinline__ void cp_async16(uint32_t dst, const void* src) {
    asm volatile("cp.async.ca.shared.global [%0], [%1], 16;" :: "r"(dst), "l"(src));
}
#define CP_COMMIT() asm volatile("cp.async.commit_group;")
#define CP_WAIT0()  asm volatile("cp.async.wait_group 0;")

// ============================================================
// K_padT: zero-pad + TRANSPOSE x into g_xp[b][hw_p][c]  |  pack w_out
//  w_out pack (rows pitch 192, group spacing 48B):
//   chunk c2 = n*2 + (ci>>5); row R = c2*16 + ((ci&31)>>1)
//   col = g*12 + o2*2 + q   (g=oc>>2, o2=oc&3, q=ci&1)
// ============================================================
#define PAD_BLKS (B_*HP_)
#define W0_BLKS  ((KTOT*C_ + 255)/256)
__global__ __launch_bounds__(256)
void k_padT(const float* __restrict__ x, const float* __restrict__ w) {
    int blk = blockIdx.x;
    int tid = threadIdx.x;
    if (blk < PAD_BLKS) {
        __shared__ float ts[WP_ * 65];     // [w][c] pitch 65 (conflict-free)
        int b = blk / HP_, h = blk % HP_;
        if (h >= 1 && h <= H_) {
            const float* xr = x + (size_t)b * C_ * HW_ + (h - 1) * W_;
#pragma unroll 4
            for (int e = tid; e < C_ * W_; e += 256) {
                int c = e >> 7, w2 = e & 127;            // coalesced read along w
                ts[(w2 + 1) * 65 + c] = xr[c * HW_ + w2];
            }
            if (tid < 2 * C_) {                          // border columns
                int c = tid & 63, side = tid >> 6;
                ts[(side ? (WP_ - 1) * 65 : 0) + c] = 0.f;
            }
        } else {
            for (int e = tid; e < WP_ * C_; e += 256) {
                int w2 = e >> 6, c = e & 63;
                ts[w2 * 65 + c] = 0.f;
            }
        }
        __syncthreads();
        float* dst = g_xp + ((size_t)b * HP_ + h) * WP_ * C_;
#pragma unroll 4
        for (int e = tid; e < WP_ * C_; e += 256) {
            int w2 = e >> 6, c = e & 63;
            dst[e] = ts[w2 * 65 + c];                    // coalesced write along c
        }
    } else {
        int t = (blk - PAD_BLKS) * 256 + tid;
        if (t < KTOT * C_) {
            int oc = t / KTOT, r = t - oc * KTOT;        // r = ci*9 + n
            int ci = r / 9, n = r - ci * 9;
            int c2 = n * 2 + (ci >> 5);
            int R  = c2 * 16 + ((ci & 31) >> 1);
            int q  = ci & 1;
            int g  = oc >> 2, o2 = oc & 3;
            int col = g * 12 + o2 * 2 + q;
            g_wt2[R * 192 + col] = w[t];
        }
    }
}

// ============================================================
// K2 (fused k1+k2): f = relu(bn1(1x1(x))) computed per-tile from g_xp,
//   then off = relu(bn3(1x1( relu(bn2(3x3(f))) )))
// ============================================================
__global__ __launch_bounds__(256)
void k2_offsets(const float* __restrict__ w1,
                const float* __restrict__ g1, const float* __restrict__ b1,
                const float* __restrict__ m1, const float* __restrict__ v1,
                const float* __restrict__ wdw,
                const float* __restrict__ g2, const float* __restrict__ b2,
                const float* __restrict__ m2, const float* __restrict__ v2,
                const float* __restrict__ wc2,
                const float* __restrict__ g3, const float* __restrict__ b3,
                const float* __restrict__ m3, const float* __restrict__ v3) {
    __shared__ float fs[HID * 18 * 18];
    __shared__ float ws[C_][HID];
    __shared__ float wdw_s[OFC * HID * 9];
    __shared__ float wc2_s[OFC * OFC];
    __shared__ float inv1_s[HID], beta1_s[HID];
    __shared__ float inv2_s[OFC], beta2_s[OFC], inv3_s[OFC], beta3_s[OFC];
    int tid = threadIdx.x;

    int blk = blockIdx.x;
    int b = blk >> 6, t = blk & 63;
    int h0 = (t >> 3) << 4, w0 = (t & 7) << 4;

    for (int e = tid; e < HID * C_; e += 256) {
        int o = e / C_, c = e % C_;
        ws[c][o] = w1[e];
    }
    for (int e = tid; e < OFC * HID * 9; e += 256) wdw_s[e] = wdw[e];
    for (int e = tid; e < OFC * OFC; e += 256)     wc2_s[e] = wc2[e];
    if (tid < HID) {
        float i1 = g1[tid] * rsqrtf(v1[tid] + 1e-5f);
        inv1_s[tid] = i1; beta1_s[tid] = b1[tid] - m1[tid] * i1;
    }
    if (tid < OFC) {
        float i2 = g2[tid] * rsqrtf(v2[tid] + 1e-5f);
        inv2_s[tid] = i2; beta2_s[tid] = b2[tid] - m2[tid] * i2;
        float i3 = g3[tid] * rsqrtf(v3[tid] + 1e-5f);
        inv3_s[tid] = i3; beta3_s[tid] = b3[tid] - m3[tid] * i3;
    }
    __syncthreads();

    // ---- f halo from padded transposed x: 18x18 px, 16 outputs each ----
    const float* xpb = g_xp + (size_t)b * HWP_ * C_;
    for (int e = tid; e < 324; e += 256) {
        int hh = e / 18, ww = e - hh * 18;
        int h = h0 - 1 + hh, w = w0 - 1 + ww;
        if (h >= 0 && h < H_ && w >= 0 && w < W_) {
            const float4* xr = (const float4*)(xpb + ((h + 1) * WP_ + (w + 1)) * C_);
            float acc[HID];
#pragma unroll
            for (int o = 0; o < HID; o++) acc[o] = 0.f;
#pragma unroll 4
            for (int c4 = 0; c4 < 16; c4++) {
                float4 xv = xr[c4];
                const float* wr = &ws[c4 * 4][0];
#pragma unroll
                for (int o = 0; o < HID; o++) acc[o] += wr[o] * xv.x;
#pragma unroll
                for (int o = 0; o < HID; o++) acc[o] += wr[HID + o] * xv.y;
#pragma unroll
                for (int o = 0; o < HID; o++) acc[o] += wr[2 * HID + o] * xv.z;
#pragma unroll
                for (int o = 0; o < HID; o++) acc[o] += wr[3 * HID + o] * xv.w;
            }
#pragma unroll
            for (int o = 0; o < HID; o++)
                fs[o * 324 + e] = fmaxf(acc[o] * inv1_s[o] + beta1_s[o], 0.f);
        } else {
#pragma unroll
            for (int o = 0; o < HID; o++) fs[o * 324 + e] = 0.f;
        }
    }
    __syncthreads();

    int ty2 = tid >> 4, tx2 = tid & 15;
    float acc[OFC];
#pragma unroll
    for (int o = 0; o < OFC; o++) acc[o] = 0.f;

    for (int ci = 0; ci < HID; ci++) {
        float fv[9];
        const float* fsc = fs + ci * 324;
#pragma unroll
        for (int dh = 0; dh < 3; dh++)
#pragma unroll
            for (int dw = 0; dw < 3; dw++)
                fv[dh * 3 + dw] = fsc[(ty2 + dh) * 18 + (tx2 + dw)];
        const float* wp = wdw_s + ci * 9;
#pragma unroll
        for (int o = 0; o < OFC; o++) {
            const float* wo = wp + o * (HID * 9);
            float a = acc[o];
#pragma unroll
            for (int k = 0; k < 9; k++) a += wo[k] * fv[k];
            acc[o] = a;
        }
    }
    float tv[OFC];
#pragma unroll
    for (int o = 0; o < OFC; o++)
        tv[o] = fmaxf(acc[o] * inv2_s[o] + beta2_s[o], 0.f);

    int h = h0 + ty2, w = w0 + tx2;
    float* op = g_off + (size_t)b * OFC * HW_ + h * W_ + w;
#pragma unroll
    for (int o2 = 0; o2 < OFC; o2++) {
        float a = 0.f;
#pragma unroll
        for (int o = 0; o < OFC; o++) a += wc2_s[o2 * OFC + o] * tv[o];
        op[o2 * HW_] = fmaxf(a * inv3_s[o2] + beta3_s[o2], 0.f);
    }
}

// ============================================================
// K3: fused bilinear sampler + SGEMM (k-paired f32x2), 8px x 4oc tiles
//   gather: 4 px/iter, float4 channel quads (half the instructions)
//   bank-swizzled B (48B group spacing); smem 96KB -> 2 CTAs/SM
// ============================================================
#define APITCH 36
#define SLABN (128*APITCH)                  // 4608 floats per slab buffer
#define BCH   3072                          // floats per B chunk (16 kp x 192)
#define SMEM_WGT  18432                     // wgt4 after idx4 (1152 x 16B each)
#define SMEM_SLAB 36864
#define SMEM_B    (SMEM_SLAB + 2*SLABN*4)   // 73728
#define K3_SMEM   (SMEM_B + 2*BCH*4)        // 98304

__global__ __launch_bounds__(256, 2)
void k3_main(const float* __restrict__ x, float* __restrict__ out) {
    extern __shared__ char smem[];
    int4*   idx_s = (int4*)smem;                   // [128 px][9 pts]
    float4* wgt_s = (float4*)(smem + SMEM_WGT);    // [128 px][9 pts]
    float*  slab  = (float*)(smem + SMEM_SLAB);    // [2][128][APITCH]
    float*  bsm   = (float*)(smem + SMEM_B);       // [2][BCH]

    int tid = threadIdx.x;
    int blk = blockIdx.x;                 // 256 blocks
    int b = blk >> 7;
    int tile = blk & 127;
    int h0 = (tile >> 3) << 3;            // 16 h-tiles of 8
    int w0 = (tile & 7) << 4;             // 8 w-tiles of 16

    // B staging: 12288 B per chunk, 3 x 16B per thread (coalesced)
    uint32_t bsm_u32 = (uint32_t)__cvta_generic_to_shared(bsm) + tid * 48;
#define STAGE_B(buf, cc)                                                      \
    {                                                                         \
        const float* src = g_wt2 + (cc) * BCH + tid * 12;                     \
        uint32_t dst = bsm_u32 + (buf) * (BCH*4);                             \
        cp_async16(dst,      src);                                            \
        cp_async16(dst + 16, src + 4);                                        \
        cp_async16(dst + 32, src + 8);                                        \
        CP_COMMIT();                                                          \
    }

    STAGE_B(0, 0)

    // ---- full bilinear metadata: indices (pre-scaled) + final weights ----
    const float* offp = g_off + (size_t)b * OFC * HW_;
    for (int e = tid; e < 128 * NPT; e += 256) {
        int px = e / 9, n = e - px * 9;
        int h = h0 + (px >> 4), w = w0 + (px & 15);
        int hw = h * W_ + w;
        float offx = offp[n * HW_ + hw];
        float offy = offp[(NPT + n) * HW_ + hw];
        float pxf = (float)(h + 1) + (float)(n / 3 - 1) + offx;
        float pyf = (float)(w + 1) + (float)(n % 3 - 1) + offy;
        float flx = floorf(pxf), fly = floorf(pyf);
        float qltx = fminf(fmaxf(flx, 0.f), 129.f);
        float qlty = fminf(fmaxf(fly, 0.f), 129.f);
        float qrbx = fminf(fmaxf(flx + 1.f, 0.f), 129.f);
        float qrby = fminf(fmaxf(fly + 1.f, 0.f), 129.f);
        float pxc = fminf(fmaxf(pxf, 0.f), 129.f);
        float pyc = fminf(fmaxf(pyf, 0.f), 129.f);
        float gxl = 1.f + qltx - pxc, gxr = 1.f - qrbx + pxc;
        float gyl = 1.f + qlty - pyc, gyr = 1.f - qrby + pyc;
        float4 g;
        g.x = gxl * gyl; g.y = gxr * gyr; g.z = gxl * gyr; g.w = gxr * gyl;
        int ltx = (int)qltx, lty = (int)qlty, rbx = (int)qrbx, rby = (int)qrby;
        int4 id;
        id.x = (ltx * WP_ + lty) << 6;    // pre-scaled by C_=64 floats
        id.y = (rbx * WP_ + rby) << 6;
        id.z = (ltx * WP_ + rby) << 6;
        id.w = (rbx * WP_ + lty) << 6;
        idx_s[e] = id;
        wgt_s[e] = g;
    }

    const float* xpb = g_xp + (size_t)b * HWP_ * C_;
    const int lane = tid & 31;
    const int wid  = tid >> 5;            // 0..7
    const int lc4  = lane & 7;            // channel quad within chunk
    const int pxq  = lane >> 3;           // px sub-index 0..3

    // warp-cooperative gather: warp w -> px [16w, 16w+16), 4 px per iter
#define GATHER_CHUNK(dbuf, cc)                                                \
    {                                                                         \
        int n_ = (cc) >> 1;                                                   \
        const float* xch = xpb + ((cc) & 1) * 32 + 4 * lc4;                   \
        float* sd = slab + (dbuf) * SLABN + 4 * lc4;                          \
        _Pragma("unroll")                                                     \
        for (int it = 0; it < 4; it++) {                                      \
            int px = wid * 16 + it * 4 + pxq;                                 \
            int s = px * 9 + n_;                                              \
            int4 id = idx_s[s];                                               \
            float4 g = wgt_s[s];                                              \
            float4 lt = *(const float4*)(xch + id.x);                         \
            float4 rb = *(const float4*)(xch + id.y);                         \
            float4 lb = *(const float4*)(xch + id.z);                         \
            float4 rt = *(const float4*)(xch + id.w);                         \
            float4 v;                                                         \
            v.x = g.x*lt.x + g.y*rb.x + g.z*lb.x + g.w*rt.x;                  \
            v.y = g.x*lt.y + g.y*rb.y + g.z*lb.y + g.w*rt.y;                  \
            v.z = g.x*lt.z + g.y*rb.z + g.z*lb.z + g.w*rt.z;                  \
            v.w = g.x*lt.w + g.y*rb.w + g.z*lb.w + g.w*rt.w;                  \
            *(float4*)(sd + px * APITCH) = v;                                 \
        }                                                                     \
    }

    CP_WAIT0();
    __syncthreads();               // meta + B(0) visible
    GATHER_CHUNK(0, 0)
    __syncthreads();               // slab(0) visible

    const int g  = tid & 15;       // oc-group: oc = g*4 .. g*4+3
    const int pg = tid >> 4;       // px-group: px = pg*8 .. pg*8+7

    unsigned long long acc[8][4];  // [px][oc], f32x2 (even-k, odd-k) partials
#pragma unroll
    for (int i = 0; i < 8; i++)
#pragma unroll
        for (int j = 0; j < 4; j++) acc[i][j] = 0ull;

    // ---- pipelined chunk loop ----
    for (int c = 0; c < 18; c++) {
        if (c < 17) {
            STAGE_B((c + 1) & 1, c + 1)
            GATHER_CHUNK((c + 1) & 1, c + 1)
        }

        const float* ab = slab + (c & 1) * SLABN + pg * (8 * APITCH);
        const float* bp = bsm + (c & 1) * BCH + g * 12;
#pragma unroll
        for (int dk = 0; dk < 8; dk++) {          // 2 k-pairs (4 k) per iter
            ulonglong2 av[8];
#pragma unroll
            for (int p = 0; p < 8; p++)
                av[p] = *(const ulonglong2*)(ab + p * APITCH + dk * 4);
#pragma unroll
            for (int h2 = 0; h2 < 2; h2++) {
                const float* row = bp + (dk * 2 + h2) * 192;
                ulonglong2 bv = *(const ulonglong2*)(row);       // oc j0,j1
                ulonglong2 bw = *(const ulonglong2*)(row + 4);   // oc j2,j3
#pragma unroll
                for (int p = 0; p < 8; p++) {
                    unsigned long long a = h2 ? av[p].y : av[p].x;
                    FMA2(acc[p][0], a, bv.x);
                    FMA2(acc[p][1], a, bv.y);
                    FMA2(acc[p][2], a, bw.x);
                    FMA2(acc[p][3], a, bw.y);
                }
            }
        }

        CP_WAIT0();
        __syncthreads();           // publish slab(c+1) + B(c+1)
    }

    // ---- epilogue: fold k-partials, stage via smem, coalesced residual ----
    __syncthreads();
    float* sa = (float*)smem;      // [px][65]; meta dead after last gather
#pragma unroll
    for (int p = 0; p < 8; p++) {
        int px = pg * 8 + p;
#pragma unroll
        for (int j = 0; j < 4; j++) {
            unsigned long long v = acc[p][j];
            float lo = __uint_as_float((unsigned)(v & 0xffffffffull));
            float hi = __uint_as_float((unsigned)(v >> 32));
            sa[px * 65 + g * 4 + j] = lo + hi;
        }
    }
    __syncthreads();

    for (int e = tid; e < 128 * 64; e += 256) {
        int oc = e >> 7, m = e & 127;
        int h = h0 + (m >> 4), w = w0 + (m & 15);
        int gi = ((b * C_ + oc) << 14) + (h << 7) + w;
        out[gi] = x[gi] + sa[m * 65 + oc];
    }
}

// ============================================================
extern "C" void kernel_launch(void* const* d_in, const int* in_sizes, int n_in,
                              void* d_out, int out_size) {
    const float* x       = (const float*)d_in[0];
    const float* w_conv1 = (const float*)d_in[1];
    const float* g1 = (const float*)d_in[2];
    const float* b1 = (const float*)d_in[3];
    const float* m1 = (const float*)d_in[4];
    const float* v1 = (const float*)d_in[5];
    const float* w_dw = (const float*)d_in[6];
    const float* g2 = (const float*)d_in[7];
    const float* b2 = (const float*)d_in[8];
    const float* m2 = (const float*)d_in[9];
    const float* v2 = (const float*)d_in[10];
    const float* w_conv2 = (const float*)d_in[11];
    const float* g3 = (const float*)d_in[12];
    const float* b3 = (const float*)d_in[13];
    const float* m3 = (const float*)d_in[14];
    const float* v3 = (const float*)d_in[15];
    const float* w_out = (const float*)d_in[16];
    float* out = (float*)d_out;

    cudaFuncSetAttribute(k3_main, cudaFuncAttributeMaxDynamicSharedMemorySize, K3_SMEM);

    k_padT<<<PAD_BLKS + W0_BLKS, 256>>>(x, w_out);
    k2_offsets<<<128, 256>>>(w_conv1, g1, b1, m1, v1,
                             w_dw, g2, b2, m2, v2, w_conv2, g3, b3, m3, v3);
    k3_main<<<B_ * 128, 256, K3_SMEM>>>(x, out);
}